// round 13
// baseline (speedup 1.0000x reference)
#include <cuda_runtime.h>
#include <cuda_fp16.h>
#include <cstdint>

#define NN     16384
#define EE     524288
#define STRIDE 160
#define DIN    64
#define DH     64
#define DOUT   16

#define DEG_SCALE 16777216.0f          // 2^24 fixed point for weighted degree

// ---------------- scratch ----------------------------------------------------
__device__ __align__(128) unsigned long long g_pack[NN];  // count<<32 | fixdeg
__device__ __align__(128) float   g_dinv[NN];
__device__ __align__(128) int2    g_adj [NN * STRIDE];    // (nbr, bitcast hw)
__device__ __align__(128) float   g_Y1 [NN * DH];
__device__ __align__(128) __half  g_Y1h[NN * DH];
__device__ __align__(128) float   g_Y2 [NN * DOUT];
__device__ __align__(128) __half  g_Y2h[NN * DOUT];

// ---------------- build -------------------------------------------------------

__global__ void k_init() {
    int i = blockIdx.x * blockDim.x + threadIdx.x;
    if (i < NN) g_pack[i] = 0ull;
}

// 4 edges/thread: packed count+degree atomic; returned count == slot
__global__ void k_build(const int* __restrict__ ei, const float* __restrict__ ew) {
    int t = blockIdx.x * blockDim.x + threadIdx.x;
    int e0 = t * 4;
    if (e0 >= EE) return;
    int4   r4 = *(const int4*)(ei + e0);
    int4   c4 = *(const int4*)(ei + EE + e0);
    float4 w4 = *(const float4*)(ew + e0);
    float hw[4] = {0.5f * w4.x, 0.5f * w4.y, 0.5f * w4.z, 0.5f * w4.w};
    int   rr[4] = {r4.x, r4.y, r4.z, r4.w};
    int   cc[4] = {c4.x, c4.y, c4.z, c4.w};

    unsigned sr[4], sc[4];
    #pragma unroll
    for (int q = 0; q < 4; ++q) {
        unsigned long long a =
            (1ull << 32) | (unsigned)__float2uint_rn(hw[q] * DEG_SCALE);
        sr[q] = (unsigned)(atomicAdd(&g_pack[rr[q]], a) >> 32);
        sc[q] = (unsigned)(atomicAdd(&g_pack[cc[q]], a) >> 32);
    }
    #pragma unroll
    for (int q = 0; q < 4; ++q) {
        int h = __float_as_int(hw[q]);
        if (sr[q] < STRIDE) g_adj[rr[q] * STRIDE + sr[q]] = make_int2(cc[q], h);
        if (sc[q] < STRIDE) g_adj[cc[q] * STRIDE + sc[q]] = make_int2(rr[q], h);
    }
}

// dinv + zero-pad 8 adjacency slots past each node's count (branch-free gathers)
__global__ void k_dinv() {
    int i = blockIdx.x * blockDim.x + threadIdx.x;
    if (i >= NN) return;
    unsigned long long p = g_pack[i];
    float deg = (float)(unsigned)(p & 0xffffffffull) * (1.0f / DEG_SCALE);
    g_dinv[i] = rsqrtf(deg + 1.0f);
    int n = (int)(p >> 32);
    int end = n + 8 < STRIDE ? n + 8 : STRIDE;
    for (int j = n; j < end; ++j)
        g_adj[i * STRIDE + j] = make_int2(0, 0);
}

// ---------------- dense math --------------------------------------------------

// Y1 = dinv * (x @ W1).  16 rows/block, grid 1024, 128 thr, 2x4 tiles, k x4.
__global__ void __launch_bounds__(128) k_gemm1(const float* __restrict__ x,
                                               const float* __restrict__ W1) {
    __shared__ float  Ws[DIN * DH];       // 16 KB, Ws[k][n]
    __shared__ float4 xs4[16 * 17];       // row stride 17 float4
    int tid = threadIdx.x;
    int row0 = blockIdx.x * 16;

    const float4* w4 = (const float4*)W1;
    float4* ws4 = (float4*)Ws;
    #pragma unroll
    for (int i = 0; i < 8; ++i) ws4[tid + 128 * i] = w4[tid + 128 * i];

    const float4* x4 = (const float4*)(x + row0 * DIN);
    #pragma unroll
    for (int i = 0; i < 2; ++i) {
        int p = tid + 128 * i;            // 256 float4 = 16 rows x 16
        int r = p >> 4, kq = p & 15;
        xs4[r * 17 + kq] = x4[p];
    }
    __syncthreads();

    int cx = (tid & 15) * 4;
    int ty = tid >> 4;                    // 0..7 -> rows ty*2, ty*2+1
    float acc[2][4] = {};

    #pragma unroll
    for (int kq = 0; kq < 16; ++kq) {     // 4 k per iter
        float4 xv0 = xs4[(ty * 2 + 0) * 17 + kq];
        float4 xv1 = xs4[(ty * 2 + 1) * 17 + kq];
        float4 w0 = *(const float4*)(Ws + (4 * kq + 0) * DH + cx);
        float4 w1 = *(const float4*)(Ws + (4 * kq + 1) * DH + cx);
        float4 w2 = *(const float4*)(Ws + (4 * kq + 2) * DH + cx);
        float4 w3 = *(const float4*)(Ws + (4 * kq + 3) * DH + cx);
        #pragma unroll
        for (int r = 0; r < 2; ++r) {
            float4 xv = r == 0 ? xv0 : xv1;
            acc[r][0] = fmaf(xv.x, w0.x, acc[r][0]);
            acc[r][1] = fmaf(xv.x, w0.y, acc[r][1]);
            acc[r][2] = fmaf(xv.x, w0.z, acc[r][2]);
            acc[r][3] = fmaf(xv.x, w0.w, acc[r][3]);
            acc[r][0] = fmaf(xv.y, w1.x, acc[r][0]);
            acc[r][1] = fmaf(xv.y, w1.y, acc[r][1]);
            acc[r][2] = fmaf(xv.y, w1.z, acc[r][2]);
            acc[r][3] = fmaf(xv.y, w1.w, acc[r][3]);
            acc[r][0] = fmaf(xv.z, w2.x, acc[r][0]);
            acc[r][1] = fmaf(xv.z, w2.y, acc[r][1]);
            acc[r][2] = fmaf(xv.z, w2.z, acc[r][2]);
            acc[r][3] = fmaf(xv.z, w2.w, acc[r][3]);
            acc[r][0] = fmaf(xv.w, w3.x, acc[r][0]);
            acc[r][1] = fmaf(xv.w, w3.y, acc[r][1]);
            acc[r][2] = fmaf(xv.w, w3.z, acc[r][2]);
            acc[r][3] = fmaf(xv.w, w3.w, acc[r][3]);
        }
    }

    #pragma unroll
    for (int r = 0; r < 2; ++r) {
        int row = row0 + ty * 2 + r;
        float dv = g_dinv[row];
        float4 v = make_float4(dv * acc[r][0], dv * acc[r][1],
                               dv * acc[r][2], dv * acc[r][3]);
        *(float4*)(g_Y1 + row * DH + cx) = v;
        half2 h0 = __floats2half2_rn(v.x, v.y);
        half2 h1 = __floats2half2_rn(v.z, v.w);
        *(uint2*)(g_Y1h + row * DH + cx) =
            make_uint2(*(unsigned*)&h0, *(unsigned*)&h1);
    }
}

// Fused gather1 + layer2: per node (one warp)
//   z   = Y1[node] + sum_nbr hw * Y1h[nbr]        (gather, 16 lanes x float4)
//   h   = relu(dinv*z + b1)                        (in registers)
//   Y2  = dinv * (h @ W2)                          (half-warp per 8 outputs)
__global__ void __launch_bounds__(256) k_prop1(const float* __restrict__ b1,
                                               const float* __restrict__ W2) {
    __shared__ float W2T[DOUT * DIN];     // [j][k], transposed, 4 KB
    int tid = threadIdx.x;
    #pragma unroll
    for (int i = 0; i < 4; ++i) {
        int p = tid + 256 * i;            // 1024 entries
        int k = p >> 4, j = p & 15;
        W2T[j * DIN + k] = W2[p];
    }
    __syncthreads();

    int node = (blockIdx.x * 256 + tid) >> 5;
    int lane = tid & 31;
    int half = lane >> 4;
    int l4   = (lane & 15) * 4;

    int start = node * STRIDE;
    int n     = (int)(g_pack[node] >> 32);
    int m     = (n + 7) & ~7;
    if (m > STRIDE) m = STRIDE;
    float4 acc = make_float4(0.f, 0.f, 0.f, 0.f);

    for (int j = half * 2; j < m; j += 8) {
        int4 p0 = *(const int4*)(g_adj + start + j);
        int4 p1 = *(const int4*)(g_adj + start + j + 4);
        uint2 y0 = *(const uint2*)(g_Y1h + p0.x * DH + l4);
        uint2 y1 = *(const uint2*)(g_Y1h + p0.z * DH + l4);
        uint2 y2 = *(const uint2*)(g_Y1h + p1.x * DH + l4);
        uint2 y3 = *(const uint2*)(g_Y1h + p1.z * DH + l4);
        float w0 = __int_as_float(p0.y), w1 = __int_as_float(p0.w);
        float w2 = __int_as_float(p1.y), w3 = __int_as_float(p1.w);
        float2 a, b;
        a = __half22float2(*(half2*)&y0.x); b = __half22float2(*(half2*)&y0.y);
        acc.x = fmaf(w0, a.x, acc.x); acc.y = fmaf(w0, a.y, acc.y);
        acc.z = fmaf(w0, b.x, acc.z); acc.w = fmaf(w0, b.y, acc.w);
        a = __half22float2(*(half2*)&y1.x); b = __half22float2(*(half2*)&y1.y);
        acc.x = fmaf(w1, a.x, acc.x); acc.y = fmaf(w1, a.y, acc.y);
        acc.z = fmaf(w1, b.x, acc.z); acc.w = fmaf(w1, b.y, acc.w);
        a = __half22float2(*(half2*)&y2.x); b = __half22float2(*(half2*)&y2.y);
        acc.x = fmaf(w2, a.x, acc.x); acc.y = fmaf(w2, a.y, acc.y);
        acc.z = fmaf(w2, b.x, acc.z); acc.w = fmaf(w2, b.y, acc.w);
        a = __half22float2(*(half2*)&y3.x); b = __half22float2(*(half2*)&y3.y);
        acc.x = fmaf(w3, a.x, acc.x); acc.y = fmaf(w3, a.y, acc.y);
        acc.z = fmaf(w3, b.x, acc.z); acc.w = fmaf(w3, b.y, acc.w);
    }

    // merge halves: now BOTH halves hold the full neighbor sum
    acc.x += __shfl_xor_sync(~0u, acc.x, 16);
    acc.y += __shfl_xor_sync(~0u, acc.y, 16);
    acc.z += __shfl_xor_sync(~0u, acc.z, 16);
    acc.w += __shfl_xor_sync(~0u, acc.w, 16);

    float dv = g_dinv[node];
    float4 self = *(const float4*)(g_Y1 + node * DH + l4);
    float4 bb   = *(const float4*)(b1 + l4);
    float4 h;
    h.x = fmaxf(dv * (self.x + acc.x) + bb.x, 0.0f);
    h.y = fmaxf(dv * (self.y + acc.y) + bb.y, 0.0f);
    h.z = fmaxf(dv * (self.z + acc.z) + bb.z, 0.0f);
    h.w = fmaxf(dv * (self.w + acc.w) + bb.w, 0.0f);

    // half computes outputs j = half*8 .. half*8+7 ; lane covers k = l4..l4+3
    float p[8];
    const float* wb = W2T + half * 8 * DIN + l4;
    #pragma unroll
    for (int jj = 0; jj < 8; ++jj) {
        float4 w = *(const float4*)(wb + jj * DIN);
        p[jj] = h.x * w.x + h.y * w.y + h.z * w.z + h.w * w.w;
    }
    #pragma unroll
    for (int d = 1; d < 16; d <<= 1) {
        #pragma unroll
        for (int jj = 0; jj < 8; ++jj)
            p[jj] += __shfl_xor_sync(~0u, p[jj], d);
    }

    if ((lane & 15) == 0) {
        int j0 = half * 8;
        float4 v0 = make_float4(dv * p[0], dv * p[1], dv * p[2], dv * p[3]);
        float4 v1 = make_float4(dv * p[4], dv * p[5], dv * p[6], dv * p[7]);
        *(float4*)(g_Y2 + node * DOUT + j0)     = v0;
        *(float4*)(g_Y2 + node * DOUT + j0 + 4) = v1;
        half2 h0 = __floats2half2_rn(v0.x, v0.y);
        half2 h1 = __floats2half2_rn(v0.z, v0.w);
        half2 h2 = __floats2half2_rn(v1.x, v1.y);
        half2 h3 = __floats2half2_rn(v1.z, v1.w);
        *(uint2*)(g_Y2h + node * DOUT + j0) =
            make_uint2(*(unsigned*)&h0, *(unsigned*)&h1);
        *(uint2*)(g_Y2h + node * DOUT + j0 + 4) =
            make_uint2(*(unsigned*)&h2, *(unsigned*)&h3);
    }
}

// out = dinv*(Y2 + sum hw*Y2h[nbr]) + b2.  Warp/node, branch-free, fused epilogue.
__global__ void __launch_bounds__(256) k_gather2(float* __restrict__ out,
                                                 const float* __restrict__ b2) {
    int node = (blockIdx.x * 256 + threadIdx.x) >> 5;
    int lane = threadIdx.x & 31;
    int grp  = lane >> 2;
    int l4   = (lane & 3) * 4;

    int start = node * STRIDE;
    int n     = (int)(g_pack[node] >> 32);
    int m     = (n + 7) & ~7;
    if (m > STRIDE) m = STRIDE;
    float4 acc = make_float4(0.f, 0.f, 0.f, 0.f);

    for (int j = grp; j < m; j += 8) {
        int2 e = g_adj[start + j];
        uint2 y = *(const uint2*)(g_Y2h + e.x * DOUT + l4);
        float w = __int_as_float(e.y);
        float2 a = __half22float2(*(half2*)&y.x);
        float2 b = __half22float2(*(half2*)&y.y);
        acc.x = fmaf(w, a.x, acc.x); acc.y = fmaf(w, a.y, acc.y);
        acc.z = fmaf(w, b.x, acc.z); acc.w = fmaf(w, b.y, acc.w);
    }

    #pragma unroll
    for (int d = 4; d < 32; d <<= 1) {
        acc.x += __shfl_xor_sync(~0u, acc.x, d);
        acc.y += __shfl_xor_sync(~0u, acc.y, d);
        acc.z += __shfl_xor_sync(~0u, acc.z, d);
        acc.w += __shfl_xor_sync(~0u, acc.w, d);
    }

    if (grp == 0) {
        float dv = g_dinv[node];
        float4 self = *(const float4*)(g_Y2 + node * DOUT + l4);
        float4 bb   = *(const float4*)(b2 + l4);
        *(float4*)(out + node * DOUT + l4) =
            make_float4(dv * (self.x + acc.x) + bb.x,
                        dv * (self.y + acc.y) + bb.y,
                        dv * (self.z + acc.z) + bb.z,
                        dv * (self.w + acc.w) + bb.w);
    }
}

// ---------------- launch ------------------------------------------------------

extern "C" void kernel_launch(void* const* d_in, const int* in_sizes, int n_in,
                              void* d_out, int out_size) {
    const float* x  = (const float*)d_in[0];
    const float* W1 = (const float*)d_in[1];
    const float* b1 = (const float*)d_in[2];
    const float* W2 = (const float*)d_in[3];
    const float* b2 = (const float*)d_in[4];
    const float* ew = (const float*)d_in[5];
    const int*   ei = (const int*)d_in[6];
    float* out = (float*)d_out;

    k_init   <<<NN / 256,  256>>>();
    k_build  <<<EE / 1024, 256>>>(ei, ew);
    k_dinv   <<<NN / 256,  256>>>();
    k_gemm1  <<<NN / 16,   128>>>(x, W1);
    k_prop1  <<<NN / 8,    256>>>(b1, W2);
    k_gather2<<<NN / 8,    256>>>(out, b2);
}

// round 14
// speedup vs baseline: 1.0780x; 1.0780x over previous
#include <cuda_runtime.h>
#include <cuda_fp16.h>
#include <cstdint>

#define NN     16384
#define EE     524288
#define STRIDE 160
#define DIN    64
#define DH     64
#define DOUT   16

#define DEG_SCALE 16777216.0f          // 2^24 fixed point for weighted degree

// ---------------- scratch ----------------------------------------------------
__device__ __align__(128) unsigned long long g_pack[NN];  // count<<32 | fixdeg (zeroed by gather2)
__device__ __align__(128) float   g_dinv[NN];
__device__ __align__(128) int2    g_adj [NN * STRIDE];    // (nbr, bitcast hw)
__device__ __align__(128) float   g_Y1 [NN * DH];
__device__ __align__(128) __half  g_Y1h[NN * DH];
__device__ __align__(128) float   g_Y2 [NN * DOUT];
__device__ __align__(128) __half  g_Y2h[NN * DOUT];

// ---------------- build -------------------------------------------------------

// 4 edges/thread: packed count+degree atomic; returned count == slot
__global__ void k_build(const int* __restrict__ ei, const float* __restrict__ ew) {
    int t = blockIdx.x * blockDim.x + threadIdx.x;
    int e0 = t * 4;
    if (e0 >= EE) return;
    int4   r4 = *(const int4*)(ei + e0);
    int4   c4 = *(const int4*)(ei + EE + e0);
    float4 w4 = *(const float4*)(ew + e0);
    float hw[4] = {0.5f * w4.x, 0.5f * w4.y, 0.5f * w4.z, 0.5f * w4.w};
    int   rr[4] = {r4.x, r4.y, r4.z, r4.w};
    int   cc[4] = {c4.x, c4.y, c4.z, c4.w};

    unsigned sr[4], sc[4];
    #pragma unroll
    for (int q = 0; q < 4; ++q) {
        unsigned long long a =
            (1ull << 32) | (unsigned)__float2uint_rn(hw[q] * DEG_SCALE);
        sr[q] = (unsigned)(atomicAdd(&g_pack[rr[q]], a) >> 32);
        sc[q] = (unsigned)(atomicAdd(&g_pack[cc[q]], a) >> 32);
    }
    #pragma unroll
    for (int q = 0; q < 4; ++q) {
        int h = __float_as_int(hw[q]);
        if (sr[q] < STRIDE) g_adj[rr[q] * STRIDE + sr[q]] = make_int2(cc[q], h);
        if (sc[q] < STRIDE) g_adj[cc[q] * STRIDE + sc[q]] = make_int2(rr[q], h);
    }
}

// ---------------- dense math --------------------------------------------------

// Y1 = dinv * (x @ W1) + inline dinv computation + adjacency padding.
// 32 rows/block, grid 512, 128 thr, 4x4 tiles, k unrolled x4.
__global__ void __launch_bounds__(128) k_gemm1(const float* __restrict__ x,
                                               const float* __restrict__ W1) {
    __shared__ float  Ws[DIN * DH];       // 16 KB, Ws[k][n]
    __shared__ float4 xs4[32 * 17];       // row stride 17 float4
    __shared__ float  sdinv[32];
    int tid = threadIdx.x;
    int row0 = blockIdx.x * 32;

    // dinv + branch-free padding for this block's 32 rows
    if (tid < 32) {
        int row = row0 + tid;
        unsigned long long p = g_pack[row];
        float deg = (float)(unsigned)(p & 0xffffffffull) * (1.0f / DEG_SCALE);
        float dv = rsqrtf(deg + 1.0f);
        sdinv[tid] = dv;
        g_dinv[row] = dv;
        int n = (int)(p >> 32);
        int end = n + 8 < STRIDE ? n + 8 : STRIDE;
        for (int j = n; j < end; ++j)
            g_adj[row * STRIDE + j] = make_int2(0, 0);
    }

    const float4* w4 = (const float4*)W1;
    float4* ws4 = (float4*)Ws;
    #pragma unroll
    for (int i = 0; i < 8; ++i) ws4[tid + 128 * i] = w4[tid + 128 * i];

    const float4* x4 = (const float4*)(x + row0 * DIN);
    #pragma unroll
    for (int i = 0; i < 4; ++i) {
        int p = tid + 128 * i;            // 512 float4 = 32 rows x 16
        int r = p >> 4, kq = p & 15;
        xs4[r * 17 + kq] = x4[p];
    }
    __syncthreads();

    int cx = (tid & 15) * 4;
    int ty = tid >> 4;                    // 0..7 -> rows ty*4..ty*4+3
    float acc[4][4] = {};

    #pragma unroll
    for (int kq = 0; kq < 16; ++kq) {     // 4 k per iter
        float4 xv0 = xs4[(ty * 4 + 0) * 17 + kq];
        float4 xv1 = xs4[(ty * 4 + 1) * 17 + kq];
        float4 xv2 = xs4[(ty * 4 + 2) * 17 + kq];
        float4 xv3 = xs4[(ty * 4 + 3) * 17 + kq];
        float4 w0 = *(const float4*)(Ws + (4 * kq + 0) * DH + cx);
        float4 w1 = *(const float4*)(Ws + (4 * kq + 1) * DH + cx);
        float4 w2 = *(const float4*)(Ws + (4 * kq + 2) * DH + cx);
        float4 w3 = *(const float4*)(Ws + (4 * kq + 3) * DH + cx);
        #pragma unroll
        for (int r = 0; r < 4; ++r) {
            float4 xv = r == 0 ? xv0 : r == 1 ? xv1 : r == 2 ? xv2 : xv3;
            acc[r][0] = fmaf(xv.x, w0.x, acc[r][0]);
            acc[r][1] = fmaf(xv.x, w0.y, acc[r][1]);
            acc[r][2] = fmaf(xv.x, w0.z, acc[r][2]);
            acc[r][3] = fmaf(xv.x, w0.w, acc[r][3]);
            acc[r][0] = fmaf(xv.y, w1.x, acc[r][0]);
            acc[r][1] = fmaf(xv.y, w1.y, acc[r][1]);
            acc[r][2] = fmaf(xv.y, w1.z, acc[r][2]);
            acc[r][3] = fmaf(xv.y, w1.w, acc[r][3]);
            acc[r][0] = fmaf(xv.z, w2.x, acc[r][0]);
            acc[r][1] = fmaf(xv.z, w2.y, acc[r][1]);
            acc[r][2] = fmaf(xv.z, w2.z, acc[r][2]);
            acc[r][3] = fmaf(xv.z, w2.w, acc[r][3]);
            acc[r][0] = fmaf(xv.w, w3.x, acc[r][0]);
            acc[r][1] = fmaf(xv.w, w3.y, acc[r][1]);
            acc[r][2] = fmaf(xv.w, w3.z, acc[r][2]);
            acc[r][3] = fmaf(xv.w, w3.w, acc[r][3]);
        }
    }

    #pragma unroll
    for (int r = 0; r < 4; ++r) {
        int rl = ty * 4 + r;
        int row = row0 + rl;
        float dv = sdinv[rl];
        float4 v = make_float4(dv * acc[r][0], dv * acc[r][1],
                               dv * acc[r][2], dv * acc[r][3]);
        *(float4*)(g_Y1 + row * DH + cx) = v;
        half2 h0 = __floats2half2_rn(v.x, v.y);
        half2 h1 = __floats2half2_rn(v.z, v.w);
        *(uint2*)(g_Y1h + row * DH + cx) =
            make_uint2(*(unsigned*)&h0, *(unsigned*)&h1);
    }
}

// Fused gather1 + layer2: per node (one warp)
__global__ void __launch_bounds__(256) k_prop1(const float* __restrict__ b1,
                                               const float* __restrict__ W2) {
    __shared__ float W2T[DOUT * DIN];     // [j][k], transposed, 4 KB
    int tid = threadIdx.x;
    #pragma unroll
    for (int i = 0; i < 4; ++i) {
        int p = tid + 256 * i;
        int k = p >> 4, j = p & 15;
        W2T[j * DIN + k] = W2[p];
    }
    __syncthreads();

    int node = (blockIdx.x * 256 + tid) >> 5;
    int lane = tid & 31;
    int half = lane >> 4;
    int l4   = (lane & 15) * 4;

    int start = node * STRIDE;
    int n     = (int)(g_pack[node] >> 32);
    int m     = (n + 7) & ~7;
    if (m > STRIDE) m = STRIDE;
    float4 acc = make_float4(0.f, 0.f, 0.f, 0.f);

    for (int j = half * 2; j < m; j += 8) {
        int4 p0 = *(const int4*)(g_adj + start + j);
        int4 p1 = *(const int4*)(g_adj + start + j + 4);
        uint2 y0 = *(const uint2*)(g_Y1h + p0.x * DH + l4);
        uint2 y1 = *(const uint2*)(g_Y1h + p0.z * DH + l4);
        uint2 y2 = *(const uint2*)(g_Y1h + p1.x * DH + l4);
        uint2 y3 = *(const uint2*)(g_Y1h + p1.z * DH + l4);
        float w0 = __int_as_float(p0.y), w1 = __int_as_float(p0.w);
        float w2 = __int_as_float(p1.y), w3 = __int_as_float(p1.w);
        float2 a, b;
        a = __half22float2(*(half2*)&y0.x); b = __half22float2(*(half2*)&y0.y);
        acc.x = fmaf(w0, a.x, acc.x); acc.y = fmaf(w0, a.y, acc.y);
        acc.z = fmaf(w0, b.x, acc.z); acc.w = fmaf(w0, b.y, acc.w);
        a = __half22float2(*(half2*)&y1.x); b = __half22float2(*(half2*)&y1.y);
        acc.x = fmaf(w1, a.x, acc.x); acc.y = fmaf(w1, a.y, acc.y);
        acc.z = fmaf(w1, b.x, acc.z); acc.w = fmaf(w1, b.y, acc.w);
        a = __half22float2(*(half2*)&y2.x); b = __half22float2(*(half2*)&y2.y);
        acc.x = fmaf(w2, a.x, acc.x); acc.y = fmaf(w2, a.y, acc.y);
        acc.z = fmaf(w2, b.x, acc.z); acc.w = fmaf(w2, b.y, acc.w);
        a = __half22float2(*(half2*)&y3.x); b = __half22float2(*(half2*)&y3.y);
        acc.x = fmaf(w3, a.x, acc.x); acc.y = fmaf(w3, a.y, acc.y);
        acc.z = fmaf(w3, b.x, acc.z); acc.w = fmaf(w3, b.y, acc.w);
    }

    acc.x += __shfl_xor_sync(~0u, acc.x, 16);
    acc.y += __shfl_xor_sync(~0u, acc.y, 16);
    acc.z += __shfl_xor_sync(~0u, acc.z, 16);
    acc.w += __shfl_xor_sync(~0u, acc.w, 16);

    float dv = g_dinv[node];
    float4 self = *(const float4*)(g_Y1 + node * DH + l4);
    float4 bb   = *(const float4*)(b1 + l4);
    float4 h;
    h.x = fmaxf(dv * (self.x + acc.x) + bb.x, 0.0f);
    h.y = fmaxf(dv * (self.y + acc.y) + bb.y, 0.0f);
    h.z = fmaxf(dv * (self.z + acc.z) + bb.z, 0.0f);
    h.w = fmaxf(dv * (self.w + acc.w) + bb.w, 0.0f);

    float p[8];
    const float* wb = W2T + half * 8 * DIN + l4;
    #pragma unroll
    for (int jj = 0; jj < 8; ++jj) {
        float4 w = *(const float4*)(wb + jj * DIN);
        p[jj] = h.x * w.x + h.y * w.y + h.z * w.z + h.w * w.w;
    }
    #pragma unroll
    for (int d = 1; d < 16; d <<= 1) {
        #pragma unroll
        for (int jj = 0; jj < 8; ++jj)
            p[jj] += __shfl_xor_sync(~0u, p[jj], d);
    }

    if ((lane & 15) == 0) {
        int j0 = half * 8;
        float4 v0 = make_float4(dv * p[0], dv * p[1], dv * p[2], dv * p[3]);
        float4 v1 = make_float4(dv * p[4], dv * p[5], dv * p[6], dv * p[7]);
        *(float4*)(g_Y2 + node * DOUT + j0)     = v0;
        *(float4*)(g_Y2 + node * DOUT + j0 + 4) = v1;
        half2 h0 = __floats2half2_rn(v0.x, v0.y);
        half2 h1 = __floats2half2_rn(v0.z, v0.w);
        half2 h2 = __floats2half2_rn(v1.x, v1.y);
        half2 h3 = __floats2half2_rn(v1.z, v1.w);
        *(uint2*)(g_Y2h + node * DOUT + j0) =
            make_uint2(*(unsigned*)&h0, *(unsigned*)&h1);
        *(uint2*)(g_Y2h + node * DOUT + j0 + 4) =
            make_uint2(*(unsigned*)&h2, *(unsigned*)&h3);
    }
}

// out = dinv*(Y2 + sum hw*Y2h[nbr]) + b2.  Also re-zeroes g_pack for next call.
__global__ void __launch_bounds__(256) k_gather2(float* __restrict__ out,
                                                 const float* __restrict__ b2) {
    int node = (blockIdx.x * 256 + threadIdx.x) >> 5;
    int lane = threadIdx.x & 31;
    int grp  = lane >> 2;
    int l4   = (lane & 3) * 4;

    int start = node * STRIDE;
    int n     = (int)(g_pack[node] >> 32);
    int m     = (n + 7) & ~7;
    if (m > STRIDE) m = STRIDE;
    float4 acc = make_float4(0.f, 0.f, 0.f, 0.f);

    for (int j = grp; j < m; j += 8) {
        int2 e = g_adj[start + j];
        uint2 y = *(const uint2*)(g_Y2h + e.x * DOUT + l4);
        float w = __int_as_float(e.y);
        float2 a = __half22float2(*(half2*)&y.x);
        float2 b = __half22float2(*(half2*)&y.y);
        acc.x = fmaf(w, a.x, acc.x); acc.y = fmaf(w, a.y, acc.y);
        acc.z = fmaf(w, b.x, acc.z); acc.w = fmaf(w, b.y, acc.w);
    }

    #pragma unroll
    for (int d = 4; d < 32; d <<= 1) {
        acc.x += __shfl_xor_sync(~0u, acc.x, d);
        acc.y += __shfl_xor_sync(~0u, acc.y, d);
        acc.z += __shfl_xor_sync(~0u, acc.z, d);
        acc.w += __shfl_xor_sync(~0u, acc.w, d);
    }

    if (grp == 0) {
        float dv = g_dinv[node];
        float4 self = *(const float4*)(g_Y2 + node * DOUT + l4);
        float4 bb   = *(const float4*)(b2 + l4);
        *(float4*)(out + node * DOUT + l4) =
            make_float4(dv * (self.x + acc.x) + bb.x,
                        dv * (self.y + acc.y) + bb.y,
                        dv * (self.z + acc.z) + bb.z,
                        dv * (self.w + acc.w) + bb.w);
    }
    // restore build invariant for the next kernel_launch call / graph replay
    if (lane == 0) g_pack[node] = 0ull;
}

// ---------------- launch ------------------------------------------------------

extern "C" void kernel_launch(void* const* d_in, const int* in_sizes, int n_in,
                              void* d_out, int out_size) {
    const float* x  = (const float*)d_in[0];
    const float* W1 = (const float*)d_in[1];
    const float* b1 = (const float*)d_in[2];
    const float* W2 = (const float*)d_in[3];
    const float* b2 = (const float*)d_in[4];
    const float* ew = (const float*)d_in[5];
    const int*   ei = (const int*)d_in[6];
    float* out = (float*)d_out;

    k_build  <<<EE / 1024, 256>>>(ei, ew);
    k_gemm1  <<<NN / 32,   128>>>(x, W1);
    k_prop1  <<<NN / 8,    256>>>(b1, W2);
    k_gather2<<<NN / 8,    256>>>(out, b2);
}